// round 14
// baseline (speedup 1.0000x reference)
#include <cuda_runtime.h>
#include <math.h>

#define B   32
#define NF  128
#define DE  256
#define DH  512
#define G   2
#define SL  8

// ---- device scratch (no allocations allowed) ----
__device__ float g_query[B * DE];
__device__ float g_attin[B * NF * G];
__device__ float g_finalT[B * NF * NF];  // final mask, transposed [b][m][n]
__device__ float g_attout[B * NF * G];
__device__ unsigned g_ctrB[B];           // prepB blocks done per b (reset by k3)

__device__ __forceinline__ void cp_async16(void* smem_dst, const void* gmem_src) {
    unsigned sa = (unsigned)__cvta_generic_to_shared(smem_dst);
    asm volatile("cp.async.ca.shared.global [%0], [%1], 16;" :: "r"(sa), "l"(gmem_src));
}

// ============================================================================
// Kernel 1: query (all 256 blocks) + att_in (blocks with dchunk==0).
// grid(256), block(256).
// ============================================================================
__global__ __launch_bounds__(256) void k1_query(
    const float* __restrict__ c_i, const float* __restrict__ W,
    const float* __restrict__ bias,
    const float* __restrict__ att_stack, const float* __restrict__ stack_ptr)
{
    int bid = blockIdx.x;
    int t = threadIdx.x;
    int b  = bid >> 3;
    int d0 = (bid & 7) * 32;
    __shared__ __align__(16) float qc[DH];

    if (t < 128)
        cp_async16((float4*)qc + t, (const float4*)(c_i + b * DH) + t);
    asm volatile("cp.async.commit_group;");

    int w = t >> 5, lane = t & 31;

    float4 wv[4][4];
    #pragma unroll
    for (int i = 0; i < 4; i++) {
        int d = d0 + w * 4 + i;
        const float4* Wr = (const float4*)(W + (size_t)d * DH);
        #pragma unroll
        for (int jj = 0; jj < 4; jj++)
            wv[i][jj] = Wr[lane + 32 * jj];
    }

    // att_in rides on the dchunk==0 block per b (overlaps the loads above)
    if ((bid & 7) == 0) {
        int n = t >> 1, g = t & 1;
        const float* as = att_stack + (((size_t)b * NF + n) * G + g) * SL;
        const float* sp = stack_ptr + b * SL;
        float s = 0.f;
        #pragma unroll
        for (int ss = 0; ss < SL; ss++) s += as[ss] * sp[ss];
        g_attin[(b * NF + n) * G + g] = s;
    }

    asm volatile("cp.async.wait_group 0;");
    __syncthreads();

    const float4* qc4 = (const float4*)qc;
    #pragma unroll
    for (int i = 0; i < 4; i++) {
        int d = d0 + w * 4 + i;
        float s = 0.f;
        #pragma unroll
        for (int jj = 0; jj < 4; jj++) {
            float4 q = qc4[lane + 32 * jj];
            s += wv[i][jj].x * q.x + wv[i][jj].y * q.y
               + wv[i][jj].z * q.z + wv[i][jj].w * q.w;
        }
        #pragma unroll
        for (int o = 16; o; o >>= 1) s += __shfl_xor_sync(~0u, s, o);
        if (lane == 0) g_query[b * DE + d] = s + bias[d];
    }
}

// ============================================================================
// Kernel 2: combined launch, grid(256 + B*NF), block(256).
//   bid < 256  : prepB (self-contained bitmask mask-power) -> finalT,
//                then atomicAdd(g_ctrB[b]).  Producers at lowest bids.
//   bid >= 256 : sigma + fused contraction: compute sig row in smem, then
//                (end-spin on g_ctrB[b]==8, normally already satisfied)
//                att_out[b,m,g] = sum_n attin[n,g]*finalT[m,n]*sig[n].
// ============================================================================
__global__ __launch_bounds__(256) void k2_prepB_sigma(
    const float* __restrict__ relmask, const float* __restrict__ fe)
{
    __shared__ __align__(16) char shraw[49152];
    int bid = blockIdx.x;
    int t = threadIdx.x;

    if (bid < 256) {
        // ---------------- self-contained prepB ----------------
        int b  = bid >> 3;
        int n0 = (bid & 7) * 16;
        const float* Mb = relmask + (size_t)b * NF * NF;

        unsigned (*rowbits)[4] = (unsigned(*)[4])shraw;            // 2.0KB
        unsigned (*colbits)[5] = (unsigned(*)[5])(shraw + 2048);   // 2.5KB
        float (*csh)[NF] = (float(*)[NF])(shraw + 4608);           // 8KB: P rows
        float (*msm)[NF] = (float(*)[NF])(shraw + 12800);          // 8KB: M rows
        float (*msh)[NF] = (float(*)[NF])(shraw + 20992);          // 16KB: R tile

        int w = t >> 5, lane = t & 31;

        // bit-pack M: batch 8 loads before ballots -> MLP 8
        #pragma unroll
        for (int g8 = 0; g8 < 8; g8++) {
            float v[8];
            #pragma unroll
            for (int i = 0; i < 8; i++) {
                int Wd = w + 8 * (8 * g8 + i);
                int r = Wd >> 2, ww = Wd & 3;
                v[i] = Mb[r * NF + ww * 32 + lane];
            }
            #pragma unroll
            for (int i = 0; i < 8; i++) {
                int Wd = w + 8 * (8 * g8 + i);
                int r = Wd >> 2, ww = Wd & 3;
                unsigned bal = __ballot_sync(~0u, v[i] != 0.f);
                if (lane == 0) rowbits[r][ww] = bal;
            }
        }
        __syncthreads();

        // bit transpose
        for (int p = t; p < 512; p += 256) {
            int m = p >> 2, ww = p & 3;
            unsigned x = 0;
            #pragma unroll
            for (int j = 0; j < 32; j++)
                x |= (((rowbits[32 * ww + j][m >> 5] >> (m & 31)) & 1u) << j);
            colbits[m][ww] = x;
        }
        __syncthreads();

        // left operand P rows + M rows for this block's 16 output rows
        for (int o = t; o < 16 * NF; o += 256) {
            int i = o >> 7, m = o & 127;
            int n = n0 + i;
            unsigned c = __popc(rowbits[n][0] & colbits[m][0])
                       + __popc(rowbits[n][1] & colbits[m][1])
                       + __popc(rowbits[n][2] & colbits[m][2])
                       + __popc(rowbits[n][3] & colbits[m][3]);
            csh[i][m] = (float)c;
            msm[i][m] = (float)((rowbits[n][m >> 5] >> (m & 31)) & 1u);
        }
        __syncthreads();

        int tn = (t >> 5) * 2;
        int tm = (t & 31) * 4;

        float acc0[4] = {}, acc1[4] = {};
        for (int kt = 0; kt < 4; kt++) {
            // synthesize R k-tile from bits: R[k][m] = 0.81*M + 0.729*P
            for (int o = t; o < 32 * NF; o += 256) {
                int kk = o >> 7, m = o & 127;
                int k = kt * 32 + kk;
                unsigned c = __popc(rowbits[k][0] & colbits[m][0])
                           + __popc(rowbits[k][1] & colbits[m][1])
                           + __popc(rowbits[k][2] & colbits[m][2])
                           + __popc(rowbits[k][3] & colbits[m][3]);
                float mmv = (float)((rowbits[k][m >> 5] >> (m & 31)) & 1u);
                msh[kk][m] = 0.81f * mmv + 0.729f * (float)c;
            }
            __syncthreads();

            #pragma unroll
            for (int kk4 = 0; kk4 < 8; kk4++) {
                float cva[4], cvb[4];
                *(float4*)cva = *(const float4*)&csh[tn + 0][kt * 32 + kk4 * 4];
                *(float4*)cvb = *(const float4*)&csh[tn + 1][kt * 32 + kk4 * 4];
                #pragma unroll
                for (int j = 0; j < 4; j++) {
                    float4 mv = *(const float4*)&msh[kk4 * 4 + j][tm];
                    acc0[0] += cva[j] * mv.x; acc0[1] += cva[j] * mv.y;
                    acc0[2] += cva[j] * mv.z; acc0[3] += cva[j] * mv.w;
                    acc1[0] += cvb[j] * mv.x; acc1[1] += cvb[j] * mv.y;
                    acc1[2] += cvb[j] * mv.z; acc1[3] += cvb[j] * mv.w;
                }
            }
            __syncthreads();
        }

        // f = M + 0.9*P + acc
        float4 f0, f1;
        {
            float4 mm = *(const float4*)&msm[tn + 0][tm];
            float4 pp = *(const float4*)&csh[tn + 0][tm];
            f0.x = mm.x + 0.9f * pp.x + acc0[0];
            f0.y = mm.y + 0.9f * pp.y + acc0[1];
            f0.z = mm.z + 0.9f * pp.z + acc0[2];
            f0.w = mm.w + 0.9f * pp.w + acc0[3];
            mm = *(const float4*)&msm[tn + 1][tm];
            pp = *(const float4*)&csh[tn + 1][tm];
            f1.x = mm.x + 0.9f * pp.x + acc1[0];
            f1.y = mm.y + 0.9f * pp.y + acc1[1];
            f1.z = mm.z + 0.9f * pp.z + acc1[2];
            f1.w = mm.w + 0.9f * pp.w + acc1[3];
        }
        __syncthreads();
        *(float4*)&csh[tn + 0][tm] = f0;
        *(float4*)&csh[tn + 1][tm] = f1;
        __syncthreads();
        {
            int m = t >> 1, half = (t & 1) * 8;
            float v[8];
            #pragma unroll
            for (int i = 0; i < 8; i++) v[i] = csh[half + i][m];
            float* dstT = g_finalT + ((size_t)b * NF + m) * NF + n0 + half;
            *(float4*)&dstT[0] = make_float4(v[0], v[1], v[2], v[3]);
            *(float4*)&dstT[4] = make_float4(v[4], v[5], v[6], v[7]);
        }
        __threadfence();
        __syncthreads();
        if (t == 0) atomicAdd(&g_ctrB[b], 1u);
        return;
    }

    // ---------------- sigma + fused contraction ----------------
    int id = bid - 256;
    int b = id >> 7;
    int m = id & 127;
    float* qsh = (float*)shraw;          // 1KB
    float* sig = qsh + DE;               // 0.5KB
    float* part = sig + NF;              // 8 floats: [4 warps][2]

    qsh[t] = g_query[b * DE + t];
    __syncthreads();

    int w = t >> 5, lane = t & 31;
    int qq = lane >> 3, sub = lane & 7;
    const float4* qp = (const float4*)qsh;
    const float* febase = fe + (((size_t)b * NF) * NF + m) * DE;

    float4 cur[8];
    {
        const float4* row = (const float4*)(febase + (size_t)(w + 8 * qq) * NF * DE);
        #pragma unroll
        for (int c = 0; c < 8; c++) cur[c] = __ldcs(&row[sub + 8 * c]);
    }

    #pragma unroll
    for (int j = 0; j < 4; j++) {
        float4 nxt[8];
        if (j < 3) {
            int n2 = w + 8 * (4 * (j + 1) + qq);
            const float4* row = (const float4*)(febase + (size_t)n2 * NF * DE);
            #pragma unroll
            for (int c = 0; c < 8; c++) nxt[c] = __ldcs(&row[sub + 8 * c]);
        }

        float sA = 0.f, sB = 0.f;
        #pragma unroll
        for (int c = 0; c < 8; c += 2) {
            float4 q0 = qp[sub + 8 * c];
            float4 q1 = qp[sub + 8 * (c + 1)];
            sA += cur[c].x * q0.x + cur[c].y * q0.y
                + cur[c].z * q0.z + cur[c].w * q0.w;
            sB += cur[c+1].x * q1.x + cur[c+1].y * q1.y
                + cur[c+1].z * q1.z + cur[c+1].w * q1.w;
        }
        float s = sA + sB;
        s += __shfl_xor_sync(~0u, s, 1);
        s += __shfl_xor_sync(~0u, s, 2);
        s += __shfl_xor_sync(~0u, s, 4);
        int n = w + 8 * (4 * j + qq);
        if (sub == 0) sig[n] = 1.f / (1.f + __expf(-s));

        #pragma unroll
        for (int c = 0; c < 8; c++) cur[c] = nxt[c];
    }

    // end-spin: prepB for this b is normally long finished by now
    if (t == 0) {
        while (*(volatile unsigned*)&g_ctrB[b] < 8u) __nanosleep(32);
    }
    __syncthreads();
    __threadfence();

    // contraction: att_out[b,m,g] = sum_n attin[n,g]*finalT[m,n]*sig[n]
    float p0 = 0.f, p1 = 0.f;
    if (t < NF) {
        float wgt = g_finalT[((size_t)b * NF + m) * NF + t] * sig[t];
        float2 a = ((const float2*)(g_attin + (size_t)b * NF * G))[t];
        p0 = wgt * a.x;
        p1 = wgt * a.y;
    }
    #pragma unroll
    for (int o = 16; o; o >>= 1) {
        p0 += __shfl_xor_sync(~0u, p0, o);
        p1 += __shfl_xor_sync(~0u, p1, o);
    }
    if (lane == 0 && w < 4) { part[w * 2] = p0; part[w * 2 + 1] = p1; }
    __syncthreads();
    if (t < 2) {
        float s = part[t] + part[2 + t] + part[4 + t] + part[6 + t];
        g_attout[((size_t)b * NF + m) * G + t] = s;
    }
}

// ============================================================================
// Kernel 3: slim epilogue — norm + blend + all outputs + counter reset.
// grid(B), block(512).
// ============================================================================
__global__ __launch_bounds__(512) void k3_final(
    const float* __restrict__ att_stack, const float* __restrict__ stack_ptr,
    float* __restrict__ out)
{
    int b = blockIdx.x;
    int t = threadIdx.x;
    __shared__ __align__(16) float asts[NF * G * SL];   // 8KB att_stack[b]
    __shared__ float att[NF * G];
    __shared__ float norm[G];
    __shared__ float sps[SL];

    ((float4*)asts)[t] = ((const float4*)(att_stack + (size_t)b * NF * G * SL))[t];
    if (t < NF * G) att[t] = g_attout[b * NF * G + t];
    if (t < SL) sps[t] = stack_ptr[b * SL + t];
    __syncthreads();

    if (t < 64) {
        int g = t >> 5, ln = t & 31;
        float mx = -1e30f;
        for (int i = ln; i < NF; i += 32) mx = fmaxf(mx, att[i * G + g]);
        #pragma unroll
        for (int o = 16; o; o >>= 1) mx = fmaxf(mx, __shfl_xor_sync(~0u, mx, o));
        if (ln == 0) norm[g] = (mx <= 1.f) ? 1.f : mx;
    }
    __syncthreads();

    float* ob = out + (size_t)b * NF * G * SL;
    for (int idx = t; idx < NF * G * SL; idx += 512) {
        int s = idx & 7;
        int g = (idx >> 3) & 1;
        int n = idx >> 4;
        float a  = att[n * G + g] / norm[g];
        float sp = sps[s];
        ob[idx] = a * sp + asts[idx] * (1.f - sp);
    }
    if (t < SL) out[(size_t)B * NF * G * SL + b * SL + t] = sps[t];
    float* z = out + (size_t)B * NF * G * SL + (size_t)B * SL;
    for (int i = t; i < DH; i += 512) {
        z[(size_t)b * DH + i] = 0.f;
        z[(size_t)B * DH + (size_t)b * DH + i] = 0.f;
    }

    // reset per-b prepB counter for the next graph replay
    if (t == 0) g_ctrB[b] = 0u;
}

// ============================================================================
extern "C" void kernel_launch(void* const* d_in, const int* in_sizes, int n_in,
                              void* d_out, int out_size)
{
    const float* feat_edge = (const float*)d_in[2];
    const float* c_i       = (const float*)d_in[3];
    const float* relmask   = (const float*)d_in[4];
    const float* att_stack = (const float*)d_in[5];
    const float* stack_ptr = (const float*)d_in[6];
    const float* map_c_w   = (const float*)d_in[8];
    const float* map_c_b   = (const float*)d_in[9];
    float* out = (float*)d_out;

    k1_query<<<256, 256>>>(c_i, map_c_w, map_c_b, att_stack, stack_ptr);
    k2_prepB_sigma<<<256 + B * NF, 256>>>(relmask, feat_edge);
    k3_final<<<B, 512>>>(att_stack, stack_ptr, out);
}

// round 15
// speedup vs baseline: 1.0607x; 1.0607x over previous
#include <cuda_runtime.h>
#include <math.h>

#define B   32
#define NF  128
#define DE  256
#define DH  512
#define G   2
#define SL  8

// ---- device scratch (no allocations allowed) ----
__device__ float g_query[B * DE];
__device__ float g_attin[B * NF * G];
__device__ float g_finalT[B * NF * NF];  // final mask, transposed [b][m][n]
__device__ float g_sig[B * NF * NF];     // sigmoid(fe . q), layout [b][m][n]
__device__ float g_attout[B * NF * G];

__device__ __forceinline__ void cp_async16(void* smem_dst, const void* gmem_src) {
    unsigned sa = (unsigned)__cvta_generic_to_shared(smem_dst);
    asm volatile("cp.async.ca.shared.global [%0], [%1], 16;" :: "r"(sa), "l"(gmem_src));
}

// ============================================================================
// Kernel 1: query (all 256 blocks) + att_in (blocks with dchunk==0).
// grid(256), block(256).
// ============================================================================
__global__ __launch_bounds__(256) void k1_query(
    const float* __restrict__ c_i, const float* __restrict__ W,
    const float* __restrict__ bias,
    const float* __restrict__ att_stack, const float* __restrict__ stack_ptr)
{
    int bid = blockIdx.x;
    int t = threadIdx.x;
    int b  = bid >> 3;
    int d0 = (bid & 7) * 32;
    __shared__ __align__(16) float qc[DH];

    if (t < 128)
        cp_async16((float4*)qc + t, (const float4*)(c_i + b * DH) + t);
    asm volatile("cp.async.commit_group;");

    int w = t >> 5, lane = t & 31;

    float4 wv[4][4];
    #pragma unroll
    for (int i = 0; i < 4; i++) {
        int d = d0 + w * 4 + i;
        const float4* Wr = (const float4*)(W + (size_t)d * DH);
        #pragma unroll
        for (int jj = 0; jj < 4; jj++)
            wv[i][jj] = Wr[lane + 32 * jj];
    }

    // att_in rides on the dchunk==0 block per b (overlaps the loads above)
    if ((bid & 7) == 0) {
        int n = t >> 1, g = t & 1;
        const float* as = att_stack + (((size_t)b * NF + n) * G + g) * SL;
        const float* sp = stack_ptr + b * SL;
        float s = 0.f;
        #pragma unroll
        for (int ss = 0; ss < SL; ss++) s += as[ss] * sp[ss];
        g_attin[(b * NF + n) * G + g] = s;
    }

    asm volatile("cp.async.wait_group 0;");
    __syncthreads();

    const float4* qc4 = (const float4*)qc;
    #pragma unroll
    for (int i = 0; i < 4; i++) {
        int d = d0 + w * 4 + i;
        float s = 0.f;
        #pragma unroll
        for (int jj = 0; jj < 4; jj++) {
            float4 q = qc4[lane + 32 * jj];
            s += wv[i][jj].x * q.x + wv[i][jj].y * q.y
               + wv[i][jj].z * q.z + wv[i][jj].w * q.w;
        }
        #pragma unroll
        for (int o = 16; o; o >>= 1) s += __shfl_xor_sync(~0u, s, o);
        if (lane == 0) g_query[b * DE + d] = s + bias[d];
    }
}

// ============================================================================
// Kernel 2: combined launch, grid(256 + B*NF), block(256).
//   bid < 256  : prepB (SELF-CONTAINED bitmask mask-power) -> finalT.
//   bid >= 256 : sigma stream — sig[b,m,n] = sigmoid(fe[b,n,m,:].q[b,:]).
// No cross-block sync of any kind (three rounds proved it costs 8-10us).
// ============================================================================
__global__ __launch_bounds__(256) void k2_prepB_sigma(
    const float* __restrict__ relmask, const float* __restrict__ fe)
{
    __shared__ __align__(16) char shraw[49152];
    int bid = blockIdx.x;
    int t = threadIdx.x;

    if (bid < 256) {
        // ---------------- self-contained prepB ----------------
        int b  = bid >> 3;
        int n0 = (bid & 7) * 16;
        const float* Mb = relmask + (size_t)b * NF * NF;

        unsigned (*rowbits)[4] = (unsigned(*)[4])shraw;            // 2.0KB
        unsigned (*colbits)[5] = (unsigned(*)[5])(shraw + 2048);   // 2.5KB
        float (*csh)[NF] = (float(*)[NF])(shraw + 4608);           // 8KB: P rows
        float (*msm)[NF] = (float(*)[NF])(shraw + 12800);          // 8KB: M rows
        float (*msh)[NF] = (float(*)[NF])(shraw + 20992);          // 16KB: R tile

        int w = t >> 5, lane = t & 31;

        // bit-pack M: batch 8 loads before ballots -> MLP 8
        #pragma unroll
        for (int g8 = 0; g8 < 8; g8++) {
            float v[8];
            #pragma unroll
            for (int i = 0; i < 8; i++) {
                int Wd = w + 8 * (8 * g8 + i);
                int r = Wd >> 2, ww = Wd & 3;
                v[i] = Mb[r * NF + ww * 32 + lane];
            }
            #pragma unroll
            for (int i = 0; i < 8; i++) {
                int Wd = w + 8 * (8 * g8 + i);
                int r = Wd >> 2, ww = Wd & 3;
                unsigned bal = __ballot_sync(~0u, v[i] != 0.f);
                if (lane == 0) rowbits[r][ww] = bal;
            }
        }
        __syncthreads();

        // bit transpose
        for (int p = t; p < 512; p += 256) {
            int m = p >> 2, ww = p & 3;
            unsigned x = 0;
            #pragma unroll
            for (int j = 0; j < 32; j++)
                x |= (((rowbits[32 * ww + j][m >> 5] >> (m & 31)) & 1u) << j);
            colbits[m][ww] = x;
        }
        __syncthreads();

        // left operand P rows + M rows for this block's 16 output rows
        for (int o = t; o < 16 * NF; o += 256) {
            int i = o >> 7, m = o & 127;
            int n = n0 + i;
            unsigned c = __popc(rowbits[n][0] & colbits[m][0])
                       + __popc(rowbits[n][1] & colbits[m][1])
                       + __popc(rowbits[n][2] & colbits[m][2])
                       + __popc(rowbits[n][3] & colbits[m][3]);
            csh[i][m] = (float)c;
            msm[i][m] = (float)((rowbits[n][m >> 5] >> (m & 31)) & 1u);
        }
        __syncthreads();

        int tn = (t >> 5) * 2;
        int tm = (t & 31) * 4;

        float acc0[4] = {}, acc1[4] = {};
        for (int kt = 0; kt < 4; kt++) {
            // synthesize R k-tile from bits: R[k][m] = 0.81*M + 0.729*P
            for (int o = t; o < 32 * NF; o += 256) {
                int kk = o >> 7, m = o & 127;
                int k = kt * 32 + kk;
                unsigned c = __popc(rowbits[k][0] & colbits[m][0])
                           + __popc(rowbits[k][1] & colbits[m][1])
                           + __popc(rowbits[k][2] & colbits[m][2])
                           + __popc(rowbits[k][3] & colbits[m][3]);
                float mmv = (float)((rowbits[k][m >> 5] >> (m & 31)) & 1u);
                msh[kk][m] = 0.81f * mmv + 0.729f * (float)c;
            }
            __syncthreads();

            #pragma unroll
            for (int kk4 = 0; kk4 < 8; kk4++) {
                float cva[4], cvb[4];
                *(float4*)cva = *(const float4*)&csh[tn + 0][kt * 32 + kk4 * 4];
                *(float4*)cvb = *(const float4*)&csh[tn + 1][kt * 32 + kk4 * 4];
                #pragma unroll
                for (int j = 0; j < 4; j++) {
                    float4 mv = *(const float4*)&msh[kk4 * 4 + j][tm];
                    acc0[0] += cva[j] * mv.x; acc0[1] += cva[j] * mv.y;
                    acc0[2] += cva[j] * mv.z; acc0[3] += cva[j] * mv.w;
                    acc1[0] += cvb[j] * mv.x; acc1[1] += cvb[j] * mv.y;
                    acc1[2] += cvb[j] * mv.z; acc1[3] += cvb[j] * mv.w;
                }
            }
            __syncthreads();
        }

        // f = M + 0.9*P + acc
        float4 f0, f1;
        {
            float4 mm = *(const float4*)&msm[tn + 0][tm];
            float4 pp = *(const float4*)&csh[tn + 0][tm];
            f0.x = mm.x + 0.9f * pp.x + acc0[0];
            f0.y = mm.y + 0.9f * pp.y + acc0[1];
            f0.z = mm.z + 0.9f * pp.z + acc0[2];
            f0.w = mm.w + 0.9f * pp.w + acc0[3];
            mm = *(const float4*)&msm[tn + 1][tm];
            pp = *(const float4*)&csh[tn + 1][tm];
            f1.x = mm.x + 0.9f * pp.x + acc1[0];
            f1.y = mm.y + 0.9f * pp.y + acc1[1];
            f1.z = mm.z + 0.9f * pp.z + acc1[2];
            f1.w = mm.w + 0.9f * pp.w + acc1[3];
        }
        __syncthreads();
        *(float4*)&csh[tn + 0][tm] = f0;
        *(float4*)&csh[tn + 1][tm] = f1;
        __syncthreads();
        {
            int m = t >> 1, half = (t & 1) * 8;
            float v[8];
            #pragma unroll
            for (int i = 0; i < 8; i++) v[i] = csh[half + i][m];
            float* dstT = g_finalT + ((size_t)b * NF + m) * NF + n0 + half;
            *(float4*)&dstT[0] = make_float4(v[0], v[1], v[2], v[3]);
            *(float4*)&dstT[4] = make_float4(v[4], v[5], v[6], v[7]);
        }
        return;
    }

    // ---------------- sigma stream ----------------
    int id = bid - 256;
    int b = id >> 7;
    int m = id & 127;
    float* qsh = (float*)shraw;
    float* sig = qsh + DE;

    qsh[t] = g_query[b * DE + t];
    __syncthreads();

    int w = t >> 5, lane = t & 31;
    int qq = lane >> 3, sub = lane & 7;
    const float4* qp = (const float4*)qsh;
    const float* febase = fe + (((size_t)b * NF) * NF + m) * DE;

    float4 cur[8];
    {
        const float4* row = (const float4*)(febase + (size_t)(w + 8 * qq) * NF * DE);
        #pragma unroll
        for (int c = 0; c < 8; c++) cur[c] = __ldcs(&row[sub + 8 * c]);
    }

    #pragma unroll
    for (int j = 0; j < 4; j++) {
        float4 nxt[8];
        if (j < 3) {
            int n2 = w + 8 * (4 * (j + 1) + qq);
            const float4* row = (const float4*)(febase + (size_t)n2 * NF * DE);
            #pragma unroll
            for (int c = 0; c < 8; c++) nxt[c] = __ldcs(&row[sub + 8 * c]);
        }

        float sA = 0.f, sB = 0.f;
        #pragma unroll
        for (int c = 0; c < 8; c += 2) {
            float4 q0 = qp[sub + 8 * c];
            float4 q1 = qp[sub + 8 * (c + 1)];
            sA += cur[c].x * q0.x + cur[c].y * q0.y
                + cur[c].z * q0.z + cur[c].w * q0.w;
            sB += cur[c+1].x * q1.x + cur[c+1].y * q1.y
                + cur[c+1].z * q1.z + cur[c+1].w * q1.w;
        }
        float s = sA + sB;
        s += __shfl_xor_sync(~0u, s, 1);
        s += __shfl_xor_sync(~0u, s, 2);
        s += __shfl_xor_sync(~0u, s, 4);
        int n = w + 8 * (4 * j + qq);
        if (sub == 0) sig[n] = 1.f / (1.f + __expf(-s));

        #pragma unroll
        for (int c = 0; c < 8; c++) cur[c] = nxt[c];
    }
    __syncthreads();
    if (t < NF)
        g_sig[((size_t)b * NF + m) * NF + t] = sig[t];
}

// ============================================================================
// Kernel 3: contraction only, grid(256), block(256).
// Block (b, chunk) computes att_out for 16 m-rows (8 warps x 2 rows).
// ============================================================================
__global__ __launch_bounds__(256) void k3_contract()
{
    int bid = blockIdx.x;
    int b  = bid >> 3;
    int m0 = (bid & 7) * 16;
    int t = threadIdx.x, w = t >> 5, lane = t & 31;

    __shared__ float ash[NF * G];
    ash[t] = g_attin[b * NF * G + t];
    __syncthreads();

    const float4* ap = (const float4*)ash;
    float4 a01 = ap[2 * lane], a23 = ap[2 * lane + 1];

    #pragma unroll
    for (int r = 0; r < 2; r++) {
        int m = m0 + w * 2 + r;
        const float4* fr = (const float4*)(g_finalT + ((size_t)b * NF + m) * NF);
        const float4* sr = (const float4*)(g_sig    + ((size_t)b * NF + m) * NF);
        float4 f = fr[lane];
        float4 s = sr[lane];
        float w0 = f.x * s.x, w1 = f.y * s.y, w2 = f.z * s.z, w3 = f.w * s.w;
        float p0 = w0 * a01.x + w1 * a01.z + w2 * a23.x + w3 * a23.z;
        float p1 = w0 * a01.y + w1 * a01.w + w2 * a23.y + w3 * a23.w;
        #pragma unroll
        for (int o = 16; o; o >>= 1) {
            p0 += __shfl_xor_sync(~0u, p0, o);
            p1 += __shfl_xor_sync(~0u, p1, o);
        }
        if (lane == 0) {
            g_attout[((size_t)b * NF + m) * G + 0] = p0;
            g_attout[((size_t)b * NF + m) * G + 1] = p1;
        }
    }
}

// ============================================================================
// Kernel 4: norm + blend + all outputs.  grid(B), block(256).
// ============================================================================
__global__ __launch_bounds__(256) void k4_blend(
    const float* __restrict__ att_stack, const float* __restrict__ stack_ptr,
    float* __restrict__ out)
{
    int b = blockIdx.x;
    int t = threadIdx.x;
    __shared__ float att[NF * G];
    __shared__ float norm[G];
    __shared__ float sps[SL];

    att[t] = g_attout[b * NF * G + t];
    if (t < SL) sps[t] = stack_ptr[b * SL + t];
    __syncthreads();

    if (t < 64) {
        int g = t >> 5, ln = t & 31;
        float mx = -1e30f;
        for (int i = ln; i < NF; i += 32) mx = fmaxf(mx, att[i * G + g]);
        #pragma unroll
        for (int o = 16; o; o >>= 1) mx = fmaxf(mx, __shfl_xor_sync(~0u, mx, o));
        if (ln == 0) norm[g] = (mx <= 1.f) ? 1.f : mx;
    }
    __syncthreads();

    const float* asb = att_stack + (size_t)b * NF * G * SL;
    float* ob = out + (size_t)b * NF * G * SL;
    for (int idx = t; idx < NF * G * SL; idx += 256) {
        int s = idx & 7;
        int g = (idx >> 3) & 1;
        int n = idx >> 4;
        float a  = att[n * G + g] / norm[g];
        float sp = sps[s];
        ob[idx] = a * sp + asb[idx] * (1.f - sp);
    }
    if (t < SL) out[(size_t)B * NF * G * SL + b * SL + t] = sps[t];
    float* z = out + (size_t)B * NF * G * SL + (size_t)B * SL;
    for (int i = t; i < DH; i += 256) {
        z[(size_t)b * DH + i] = 0.f;
        z[(size_t)B * DH + (size_t)b * DH + i] = 0.f;
    }
}

// ============================================================================
extern "C" void kernel_launch(void* const* d_in, const int* in_sizes, int n_in,
                              void* d_out, int out_size)
{
    const float* feat_edge = (const float*)d_in[2];
    const float* c_i       = (const float*)d_in[3];
    const float* relmask   = (const float*)d_in[4];
    const float* att_stack = (const float*)d_in[5];
    const float* stack_ptr = (const float*)d_in[6];
    const float* map_c_w   = (const float*)d_in[8];
    const float* map_c_b   = (const float*)d_in[9];
    float* out = (float*)d_out;

    k1_query<<<256, 256>>>(c_i, map_c_w, map_c_b, att_stack, stack_ptr);
    k2_prepB_sigma<<<256 + B * NF, 256>>>(relmask, feat_edge);
    k3_contract<<<256, 256>>>();
    k4_blend<<<B, 256>>>(att_stack, stack_ptr, out);
}